// round 9
// baseline (speedup 1.0000x reference)
#include <cuda_runtime.h>
#include <cuda_fp16.h>
#include <cstdint>
#include <math.h>

#define D_MODEL 1024
#define N_HEADS 16
#define HEAD_DIM 64
#define BATCH 2
#define SEQL 2048
#define MROWS (BATCH * SEQL)   // 4096

// ---------------- scratch (device globals: allocation-free rule) -----------
__device__ __half g_xh[MROWS * D_MODEL];
__device__ __half g_qh[MROWS * D_MODEL];
__device__ __half g_kh[MROWS * D_MODEL];
__device__ __half g_vh[MROWS * D_MODEL];
__device__ __half g_ath[MROWS * D_MODEL];
__device__ __half g_wqh[D_MODEL * D_MODEL];
__device__ __half g_wkh[D_MODEL * D_MODEL];
__device__ __half g_wvh[D_MODEL * D_MODEL];
__device__ __half g_woh[D_MODEL * D_MODEL];

// ---------------- helpers ---------------------------------------------------
__device__ __forceinline__ uint32_t smem_to_u32(const void* p) {
    uint32_t a;
    asm("{ .reg .u64 t; cvta.to.shared.u64 t, %1; cvt.u32.u64 %0, t; }" : "=r"(a) : "l"(p));
    return a;
}

#define CPA16(dst, src) \
    asm volatile("cp.async.cg.shared.global [%0], [%1], 16;" :: "r"(dst), "l"(src) : "memory")
#define CPCOMMIT() asm volatile("cp.async.commit_group;" ::: "memory")
#define CPWAIT0() asm volatile("cp.async.wait_group 0;" ::: "memory")
#define CPWAIT1() asm volatile("cp.async.wait_group 1;" ::: "memory")

__device__ __forceinline__ void ldsm4(uint32_t* r, uint32_t addr) {
    asm volatile("ldmatrix.sync.aligned.m8n8.x4.shared.b16 {%0,%1,%2,%3}, [%4];"
                 : "=r"(r[0]), "=r"(r[1]), "=r"(r[2]), "=r"(r[3]) : "r"(addr));
}

__device__ __forceinline__ void ldsm4t(uint32_t* r, uint32_t addr) {
    asm volatile("ldmatrix.sync.aligned.m8n8.x4.trans.shared.b16 {%0,%1,%2,%3}, [%4];"
                 : "=r"(r[0]), "=r"(r[1]), "=r"(r[2]), "=r"(r[3]) : "r"(addr));
}

__device__ __forceinline__ void mma16816(float* d, const uint32_t* a, const uint32_t* b) {
    asm volatile(
        "mma.sync.aligned.m16n8k16.row.col.f32.f16.f16.f32 "
        "{%0,%1,%2,%3}, {%4,%5,%6,%7}, {%8,%9}, {%0,%1,%2,%3};"
        : "+f"(d[0]), "+f"(d[1]), "+f"(d[2]), "+f"(d[3])
        : "r"(a[0]), "r"(a[1]), "r"(a[2]), "r"(a[3]), "r"(b[0]), "r"(b[1]));
}

__device__ __forceinline__ uint32_t packh2(float x, float y) {
    __half2 h = __floats2half2_rn(x, y);
    return *(uint32_t*)&h;
}

// ---------------------------------------------------------------------------
// converts
// ---------------------------------------------------------------------------
__global__ __launch_bounds__(256) void cvt_h_k(const float4* __restrict__ in,
                                               uint32_t* __restrict__ hi, int n4) {
    int i = blockIdx.x * blockDim.x + threadIdx.x;
    if (i >= n4) return;
    float4 v = in[i];
    hi[2 * i]     = packh2(v.x, v.y);
    hi[2 * i + 1] = packh2(v.z, v.w);
}

__global__ __launch_bounds__(256) void cvt4_h_k(
    const float4* __restrict__ w0, const float4* __restrict__ w1,
    const float4* __restrict__ w2, const float4* __restrict__ w3,
    uint32_t* __restrict__ h0, uint32_t* __restrict__ h1,
    uint32_t* __restrict__ h2, uint32_t* __restrict__ h3, int n4) {
    int i = blockIdx.x * blockDim.x + threadIdx.x;
    if (i >= n4) return;
    const float4* in; uint32_t* hi;
    switch (blockIdx.y) {
        case 0:  in = w0; hi = h0; break;
        case 1:  in = w1; hi = h1; break;
        case 2:  in = w2; hi = h2; break;
        default: in = w3; hi = h3; break;
    }
    float4 v = in[i];
    hi[2 * i]     = packh2(v.x, v.y);
    hi[2 * i + 1] = packh2(v.z, v.w);
}

// ---------------------------------------------------------------------------
// HMMA fp16 1-pass GEMM-NT body: C[m,n] = sum_k A[m,k]*B[n,k]
// CTA 128x128, BK=32, cp.async double-buffered, 2 CTAs/SM.
// OUT: 0 = fp32 C, 1 = fp16 hi (Ch)
// ---------------------------------------------------------------------------
#define GBK 32
#define GKT (D_MODEL / GBK)          // 32
#define ARR_B 10240                  // 128 rows * 80 B
#define STG_B (2 * ARR_B)            // A | B = 20480
#define GEMM_SMEM (2 * STG_B)        // 40960

template <int OUT>
__device__ __forceinline__ void gemm_body(
    char* smc, const __half* __restrict__ Ah, const __half* __restrict__ Bh,
    float* __restrict__ C, __half* __restrict__ Ch,
    int m0, int n0) {
    const uint32_t sb = smem_to_u32(smc);
    const int tid = threadIdx.x;
    const int wid = tid >> 5;
    const int lane = tid & 31;
    const int wm = wid >> 2;
    const int wn = wid & 3;

    const int lrow = tid >> 1;
    const int lhof = (tid & 1) * 16;
    const __half* pA = Ah + (size_t)(m0 + lrow) * D_MODEL + lhof;
    const __half* pB = Bh + (size_t)(n0 + lrow) * D_MODEL + lhof;
    const uint32_t sdst = (uint32_t)(lrow * 80 + (tid & 1) * 32);

    const uint32_t aoff = (uint32_t)((wm * 64 + (lane & 15)) * 80 + (lane >> 4) * 16);
    const int j8 = lane >> 3;
    const uint32_t boff = (uint32_t)((wn * 32 + ((j8 >> 1) << 3) + (lane & 7)) * 80 + (j8 & 1) * 16);

    float acc[4][4][4];
#pragma unroll
    for (int a = 0; a < 4; a++)
#pragma unroll
        for (int b = 0; b < 4; b++)
#pragma unroll
            for (int c = 0; c < 4; c++) acc[a][b][c] = 0.0f;

#define G_ISSUE(s) do {                                                       \
        const uint32_t d = sb + (uint32_t)(((s) & 1) * STG_B) + sdst;         \
        const int go = (s) * GBK;                                             \
        CPA16(d + 0 * ARR_B,      pA + go);                                   \
        CPA16(d + 0 * ARR_B + 16, pA + go + 8);                               \
        CPA16(d + 1 * ARR_B,      pB + go);                                   \
        CPA16(d + 1 * ARR_B + 16, pB + go + 8);                               \
    } while (0)

    G_ISSUE(0); CPCOMMIT();
    G_ISSUE(1); CPCOMMIT();

    for (int t = 0; t < GKT; t++) {
        CPWAIT1();
        __syncthreads();

        const uint32_t stg = sb + (uint32_t)((t & 1) * STG_B);
#pragma unroll
        for (int ks = 0; ks < 2; ks++) {
            uint32_t ah[4][4];
#pragma unroll
            for (int mt = 0; mt < 4; mt++)
                ldsm4(ah[mt], stg + 0 * ARR_B + aoff + mt * 1280 + ks * 32);
            uint32_t bh[4][2];
#pragma unroll
            for (int bt = 0; bt < 2; bt++) {
                uint32_t tmp[4];
                ldsm4(tmp, stg + 1 * ARR_B + boff + bt * 1280 + ks * 32);
                bh[2 * bt][0] = tmp[0]; bh[2 * bt][1] = tmp[1];
                bh[2 * bt + 1][0] = tmp[2]; bh[2 * bt + 1][1] = tmp[3];
            }
#pragma unroll
            for (int mt = 0; mt < 4; mt++)
#pragma unroll
                for (int nt = 0; nt < 4; nt++)
                    mma16816(acc[mt][nt], ah[mt], bh[nt]);
        }
        __syncthreads();
        if (t + 2 < GKT) G_ISSUE(t + 2);
        CPCOMMIT();
    }
#undef G_ISSUE

    const int gr = lane >> 2;
    const int gc = (lane & 3) * 2;
#pragma unroll
    for (int mt = 0; mt < 4; mt++) {
        const int row = m0 + wm * 64 + mt * 16 + gr;
#pragma unroll
        for (int nt = 0; nt < 4; nt++) {
            const int col = n0 + wn * 32 + nt * 8 + gc;
            const size_t i0 = (size_t)row * D_MODEL + col;
            const size_t i1 = (size_t)(row + 8) * D_MODEL + col;
            if (OUT == 0) {
                *(float2*)&C[i0] = make_float2(acc[mt][nt][0], acc[mt][nt][1]);
                *(float2*)&C[i1] = make_float2(acc[mt][nt][2], acc[mt][nt][3]);
            } else {
                *(uint32_t*)(Ch + i0) = packh2(acc[mt][nt][0], acc[mt][nt][1]);
                *(uint32_t*)(Ch + i1) = packh2(acc[mt][nt][2], acc[mt][nt][3]);
            }
        }
    }
}

// fused QKV projection: blockIdx.z selects weight/output; fp16-hi outputs
__global__ __launch_bounds__(256, 2) void gemm_qkv(
    const __half* __restrict__ xh,
    const __half* __restrict__ wqh, const __half* __restrict__ wkh,
    const __half* __restrict__ wvh,
    __half* __restrict__ qh, __half* __restrict__ kh, __half* __restrict__ vh) {
    extern __shared__ char smc[];
    const __half* Bh;
    __half* Ch;
    if (blockIdx.z == 0)      { Bh = wqh; Ch = qh; }
    else if (blockIdx.z == 1) { Bh = wkh; Ch = kh; }
    else                      { Bh = wvh; Ch = vh; }
    gemm_body<1>(smc, xh, Bh, nullptr, Ch, blockIdx.y * 128, blockIdx.x * 128);
}

__global__ __launch_bounds__(256, 2) void gemm_out(
    const __half* __restrict__ ath, const __half* __restrict__ woh,
    float* __restrict__ out) {
    extern __shared__ char smc[];
    gemm_body<0>(smc, ath, woh, out, nullptr, blockIdx.y * 128, blockIdx.x * 128);
}

// ---------------------------------------------------------------------------
// Flash attention on HMMA, fp16 hi-only operands. Causal. (unchanged r8)
// 256 threads = 8 warps; Q tile 128 rows (16/warp); KV tiles 64 keys.
// ---------------------------------------------------------------------------
#define FST 144
#define FARR (64 * FST)        // 9216
#define FSTG (2 * FARR)        // Kh | Vh = 18432
#define FLASH_SMEM (2 * FSTG)  // 36864

__global__ __launch_bounds__(256) void flash_mma(
    const __half* __restrict__ Qh,
    const __half* __restrict__ Kh, const __half* __restrict__ Vh,
    __half* __restrict__ Oh) {
    extern __shared__ char smc[];
    const uint32_t sb = smem_to_u32(smc);
    const int tid = threadIdx.x;
    const int w = tid >> 5;
    const int lane = tid & 31;
    const int qt = gridDim.x - 1 - blockIdx.x;   // long blocks first
    const int h = blockIdx.y;
    const int b = blockIdx.z;
    const int q0 = qt * 128;
    const int ktmax = 2 * qt + 1;

    const size_t gbase = (size_t)b * SEQL * D_MODEL + h * HEAD_DIM;

    const int r = lane >> 2;
    const int c2 = (lane & 3) * 2;

    const int sa = tid >> 7;            // 0 = Kh, 1 = Vh
    const int t2 = tid & 127;
    const int srow = t2 >> 1;
    const int shalf = t2 & 1;
    const __half* kvsrc = (sa == 0 ? Kh : Vh) + gbase + (size_t)srow * D_MODEL + shalf * 32;
    const uint32_t kvdst = (uint32_t)(sa * FARR + srow * FST + shalf * 64);

    const uint32_t qaddr = sb + (uint32_t)((w * 16 + (lane & 15)) * FST + (lane >> 4) * 16);
    const uint32_t koff = (uint32_t)(((((lane >> 4) << 3) + (lane & 7)) * FST) + ((lane >> 3) & 1) * 16);
    const uint32_t voff = (uint32_t)((((((lane >> 3) & 1) * 8) + (lane & 7)) * FST) + (lane >> 4) * 16) + FARR;

    // ---- stage Q (128 rows x 128 B) into buffer 0, grab fragments ----
    {
        const int qrow = tid >> 1;
        const int qhalf = tid & 1;
        const uint32_t d = sb + (uint32_t)(qrow * FST + qhalf * 64);
        const __half* s = Qh + gbase + (size_t)(q0 + qrow) * D_MODEL + qhalf * 32;
#pragma unroll
        for (int j = 0; j < 4; j++) CPA16(d + j * 16, s + j * 8);
    }
    CPCOMMIT(); CPWAIT0();
    __syncthreads();
    uint32_t qhf[4][4];
#pragma unroll
    for (int ks = 0; ks < 4; ks++)
        ldsm4(qhf[ks], qaddr + ks * 32);
    __syncthreads();

#define F_STAGE(kt) do {                                                      \
        const uint32_t d = sb + (uint32_t)(((kt) & 1) * FSTG) + kvdst;        \
        const __half* s = kvsrc + (size_t)(kt) * 64 * D_MODEL;                \
        CPA16(d + 0,  s);      CPA16(d + 16, s + 8);                          \
        CPA16(d + 32, s + 16); CPA16(d + 48, s + 24);                         \
    } while (0)

    F_STAGE(0); CPCOMMIT();

    float o[8][4];
#pragma unroll
    for (int nt = 0; nt < 8; nt++)
#pragma unroll
        for (int j = 0; j < 4; j++) o[nt][j] = 0.0f;
    float mA = -1e30f, mB = -1e30f, lA = 0.0f, lB = 0.0f;

    for (int kt = 0; kt <= ktmax; kt++) {
        if (kt + 1 <= ktmax) F_STAGE(kt + 1);
        CPCOMMIT();
        CPWAIT1();
        __syncthreads();

        const uint32_t stg = sb + (uint32_t)((kt & 1) * FSTG);
        const int k0 = kt * 64;

        // ---- S = Qh Kh^T ----
        float s[8][4];
#pragma unroll
        for (int nt = 0; nt < 8; nt++)
#pragma unroll
            for (int j = 0; j < 4; j++) s[nt][j] = 0.0f;

#pragma unroll
        for (int ks = 0; ks < 4; ks++) {
#pragma unroll
            for (int np = 0; np < 4; np++) {
                uint32_t th[4];
                ldsm4(th, stg + koff + np * 16 * FST + ks * 32);
                mma16816(s[2 * np],     qhf[ks], th);
                mma16816(s[2 * np + 1], qhf[ks], th + 2);
            }
        }

        // ---- scale + causal mask ----
        const bool masked = (kt >= 2 * qt);
        const int rowA = q0 + w * 16 + r;
        const int rowB = rowA + 8;
#pragma unroll
        for (int nt = 0; nt < 8; nt++)
#pragma unroll
            for (int j = 0; j < 2; j++) {
                const int colg = k0 + nt * 8 + c2 + j;
                float vA = s[nt][j] * 0.125f;
                float vB = s[nt][j + 2] * 0.125f;
                if (masked && colg > rowA) vA = -1e30f;
                if (masked && colg > rowB) vB = -1e30f;
                s[nt][j] = vA;
                s[nt][j + 2] = vB;
            }

        // ---- online softmax ----
        float mxA = -1e30f, mxB = -1e30f;
#pragma unroll
        for (int nt = 0; nt < 8; nt++) {
            mxA = fmaxf(mxA, fmaxf(s[nt][0], s[nt][1]));
            mxB = fmaxf(mxB, fmaxf(s[nt][2], s[nt][3]));
        }
        mxA = fmaxf(mxA, __shfl_xor_sync(0xffffffffu, mxA, 1));
        mxA = fmaxf(mxA, __shfl_xor_sync(0xffffffffu, mxA, 2));
        mxB = fmaxf(mxB, __shfl_xor_sync(0xffffffffu, mxB, 1));
        mxB = fmaxf(mxB, __shfl_xor_sync(0xffffffffu, mxB, 2));
        const float mnA = fmaxf(mA, mxA);
        const float mnB = fmaxf(mB, mxB);
        float suA = 0.0f, suB = 0.0f;
#pragma unroll
        for (int nt = 0; nt < 8; nt++) {
            float e0 = __expf(s[nt][0] - mnA);
            float e1 = __expf(s[nt][1] - mnA);
            float e2 = __expf(s[nt][2] - mnB);
            float e3 = __expf(s[nt][3] - mnB);
            s[nt][0] = e0; s[nt][1] = e1; s[nt][2] = e2; s[nt][3] = e3;
            suA += e0 + e1;
            suB += e2 + e3;
        }
        suA += __shfl_xor_sync(0xffffffffu, suA, 1);
        suA += __shfl_xor_sync(0xffffffffu, suA, 2);
        suB += __shfl_xor_sync(0xffffffffu, suB, 1);
        suB += __shfl_xor_sync(0xffffffffu, suB, 2);
        const float scA = __expf(mA - mnA);
        const float scB = __expf(mB - mnB);
        mA = mnA; mB = mnB;
        lA = lA * scA + suA;
        lB = lB * scB + suB;
#pragma unroll
        for (int nt = 0; nt < 8; nt++) {
            o[nt][0] *= scA; o[nt][1] *= scA;
            o[nt][2] *= scB; o[nt][3] *= scB;
        }

        // ---- O += Ph Vh ----
#pragma unroll
        for (int ks = 0; ks < 4; ks++) {
            uint32_t pha[4];
            pha[0] = packh2(s[2 * ks][0], s[2 * ks][1]);
            pha[1] = packh2(s[2 * ks][2], s[2 * ks][3]);
            pha[2] = packh2(s[2 * ks + 1][0], s[2 * ks + 1][1]);
            pha[3] = packh2(s[2 * ks + 1][2], s[2 * ks + 1][3]);
#pragma unroll
            for (int np = 0; np < 4; np++) {
                uint32_t th[4];
                ldsm4t(th, stg + voff + ks * 16 * FST + np * 32);
                mma16816(o[2 * np],     pha, th);
                mma16816(o[2 * np + 1], pha, th + 2);
            }
        }
        __syncthreads();
    }
#undef F_STAGE

    // ---- epilogue: normalize, store fp16 hi ----
    const float liA = 1.0f / lA;
    const float liB = 1.0f / lB;
    const size_t orA = gbase + (size_t)(q0 + w * 16 + r) * D_MODEL;
    const size_t orB = orA + (size_t)8 * D_MODEL;
#pragma unroll
    for (int nt = 0; nt < 8; nt++) {
        const int col = nt * 8 + c2;
        *(uint32_t*)(Oh + orA + col) = packh2(o[nt][0] * liA, o[nt][1] * liA);
        *(uint32_t*)(Oh + orB + col) = packh2(o[nt][2] * liB, o[nt][3] * liB);
    }
}

// ---------------------------------------------------------------------------
extern "C" void kernel_launch(void* const* d_in, const int* in_sizes, int n_in,
                              void* d_out, int out_size) {
    const float* x  = (const float*)d_in[0];
    const float* wq = (const float*)d_in[1];
    const float* wk = (const float*)d_in[2];
    const float* wv = (const float*)d_in[3];
    const float* wo = (const float*)d_in[4];
    float* out = (float*)d_out;

    __half *xh, *qh, *kh, *vh, *ath, *wqh, *wkh, *wvh, *woh;
    cudaGetSymbolAddress((void**)&xh, g_xh);
    cudaGetSymbolAddress((void**)&qh, g_qh);
    cudaGetSymbolAddress((void**)&kh, g_kh);
    cudaGetSymbolAddress((void**)&vh, g_vh);
    cudaGetSymbolAddress((void**)&ath, g_ath);
    cudaGetSymbolAddress((void**)&wqh, g_wqh);
    cudaGetSymbolAddress((void**)&wkh, g_wkh);
    cudaGetSymbolAddress((void**)&wvh, g_wvh);
    cudaGetSymbolAddress((void**)&woh, g_woh);

    cudaFuncSetAttribute(gemm_qkv, cudaFuncAttributeMaxDynamicSharedMemorySize, GEMM_SMEM);
    cudaFuncSetAttribute(gemm_out, cudaFuncAttributeMaxDynamicSharedMemorySize, GEMM_SMEM);
    cudaFuncSetAttribute(flash_mma, cudaFuncAttributeMaxDynamicSharedMemorySize, FLASH_SMEM);

    const int nx4 = MROWS * D_MODEL / 4;
    const int nw4 = D_MODEL * D_MODEL / 4;

    cvt_h_k<<<(nx4 + 255) / 256, 256>>>((const float4*)x, (uint32_t*)xh, nx4);
    cvt4_h_k<<<dim3((nw4 + 255) / 256, 4), 256>>>(
        (const float4*)wq, (const float4*)wk, (const float4*)wv, (const float4*)wo,
        (uint32_t*)wqh, (uint32_t*)wkh, (uint32_t*)wvh, (uint32_t*)woh, nw4);

    gemm_qkv<<<dim3(D_MODEL / 128, MROWS / 128, 3), 256, GEMM_SMEM>>>(
        xh, wqh, wkh, wvh, qh, kh, vh);

    flash_mma<<<dim3(SEQL / 128, N_HEADS, BATCH), 256, FLASH_SMEM>>>(qh, kh, vh, ath);

    gemm_out<<<dim3(D_MODEL / 128, MROWS / 128), 256, GEMM_SMEM>>>(ath, woh, out);
}

// round 10
// speedup vs baseline: 1.5510x; 1.5510x over previous
#include <cuda_runtime.h>
#include <cuda_fp16.h>
#include <cstdint>
#include <math.h>

#define D_MODEL 1024
#define N_HEADS 16
#define HEAD_DIM 64
#define BATCH 2
#define SEQL 2048
#define MROWS (BATCH * SEQL)   // 4096

// ---------------- scratch (device globals: allocation-free rule) -----------
__device__ __half g_xh[MROWS * D_MODEL];
__device__ __half g_qh[MROWS * D_MODEL];
__device__ __half g_kh[MROWS * D_MODEL];
__device__ __half g_vh[MROWS * D_MODEL];
__device__ __half g_ath[MROWS * D_MODEL];
__device__ __half g_wqh[D_MODEL * D_MODEL];
__device__ __half g_wkh[D_MODEL * D_MODEL];
__device__ __half g_wvh[D_MODEL * D_MODEL];
__device__ __half g_woh[D_MODEL * D_MODEL];

// ---------------- helpers ---------------------------------------------------
__device__ __forceinline__ uint32_t smem_to_u32(const void* p) {
    uint32_t a;
    asm("{ .reg .u64 t; cvta.to.shared.u64 t, %1; cvt.u32.u64 %0, t; }" : "=r"(a) : "l"(p));
    return a;
}

#define CPA16(dst, src) \
    asm volatile("cp.async.cg.shared.global [%0], [%1], 16;" :: "r"(dst), "l"(src) : "memory")
#define CPCOMMIT() asm volatile("cp.async.commit_group;" ::: "memory")
#define CPWAIT0() asm volatile("cp.async.wait_group 0;" ::: "memory")
#define CPWAIT2() asm volatile("cp.async.wait_group 2;" ::: "memory")

__device__ __forceinline__ void ldsm4(uint32_t* r, uint32_t addr) {
    asm volatile("ldmatrix.sync.aligned.m8n8.x4.shared.b16 {%0,%1,%2,%3}, [%4];"
                 : "=r"(r[0]), "=r"(r[1]), "=r"(r[2]), "=r"(r[3]) : "r"(addr));
}

__device__ __forceinline__ void ldsm4t(uint32_t* r, uint32_t addr) {
    asm volatile("ldmatrix.sync.aligned.m8n8.x4.trans.shared.b16 {%0,%1,%2,%3}, [%4];"
                 : "=r"(r[0]), "=r"(r[1]), "=r"(r[2]), "=r"(r[3]) : "r"(addr));
}

__device__ __forceinline__ void mma16816(float* d, const uint32_t* a, const uint32_t* b) {
    asm volatile(
        "mma.sync.aligned.m16n8k16.row.col.f32.f16.f16.f32 "
        "{%0,%1,%2,%3}, {%4,%5,%6,%7}, {%8,%9}, {%0,%1,%2,%3};"
        : "+f"(d[0]), "+f"(d[1]), "+f"(d[2]), "+f"(d[3])
        : "r"(a[0]), "r"(a[1]), "r"(a[2]), "r"(a[3]), "r"(b[0]), "r"(b[1]));
}

__device__ __forceinline__ uint32_t packh2(float x, float y) {
    __half2 h = __floats2half2_rn(x, y);
    return *(uint32_t*)&h;
}

// ---------------------------------------------------------------------------
// converts
// ---------------------------------------------------------------------------
__global__ __launch_bounds__(256) void cvt_h_k(const float4* __restrict__ in,
                                               uint32_t* __restrict__ hi, int n4) {
    int i = blockIdx.x * blockDim.x + threadIdx.x;
    if (i >= n4) return;
    float4 v = in[i];
    hi[2 * i]     = packh2(v.x, v.y);
    hi[2 * i + 1] = packh2(v.z, v.w);
}

__global__ __launch_bounds__(256) void cvt4_h_k(
    const float4* __restrict__ w0, const float4* __restrict__ w1,
    const float4* __restrict__ w2, const float4* __restrict__ w3,
    uint32_t* __restrict__ h0, uint32_t* __restrict__ h1,
    uint32_t* __restrict__ h2, uint32_t* __restrict__ h3, int n4) {
    int i = blockIdx.x * blockDim.x + threadIdx.x;
    if (i >= n4) return;
    const float4* in; uint32_t* hi;
    switch (blockIdx.y) {
        case 0:  in = w0; hi = h0; break;
        case 1:  in = w1; hi = h1; break;
        case 2:  in = w2; hi = h2; break;
        default: in = w3; hi = h3; break;
    }
    float4 v = in[i];
    hi[2 * i]     = packh2(v.x, v.y);
    hi[2 * i + 1] = packh2(v.z, v.w);
}

// ---------------------------------------------------------------------------
// HMMA fp16 1-pass GEMM-NT body: C[m,n] = sum_k A[m,k]*B[n,k]
// CTA 128x128, BK=32, cp.async 3-stage pipeline, 2 CTAs/SM.
// OUT: 0 = fp32 C, 1 = fp16 hi (Ch, scaled by cscale)
// ---------------------------------------------------------------------------
#define GBK 32
#define GKT (D_MODEL / GBK)          // 32
#define ARR_B 10240                  // 128 rows * 80 B
#define STG_B (2 * ARR_B)            // A | B = 20480
#define GEMM_SMEM (3 * STG_B)        // 61440 (3 stages)

template <int OUT>
__device__ __forceinline__ void gemm_body(
    char* smc, const __half* __restrict__ Ah, const __half* __restrict__ Bh,
    float* __restrict__ C, __half* __restrict__ Ch, float cscale,
    int m0, int n0) {
    const uint32_t sb = smem_to_u32(smc);
    const int tid = threadIdx.x;
    const int wid = tid >> 5;
    const int lane = tid & 31;
    const int wm = wid >> 2;
    const int wn = wid & 3;

    const int lrow = tid >> 1;
    const int lhof = (tid & 1) * 16;
    const __half* pA = Ah + (size_t)(m0 + lrow) * D_MODEL + lhof;
    const __half* pB = Bh + (size_t)(n0 + lrow) * D_MODEL + lhof;
    const uint32_t sdst = (uint32_t)(lrow * 80 + (tid & 1) * 32);

    const uint32_t aoff = (uint32_t)((wm * 64 + (lane & 15)) * 80 + (lane >> 4) * 16);
    const int j8 = lane >> 3;
    const uint32_t boff = (uint32_t)((wn * 32 + ((j8 >> 1) << 3) + (lane & 7)) * 80 + (j8 & 1) * 16);

    float acc[4][4][4];
#pragma unroll
    for (int a = 0; a < 4; a++)
#pragma unroll
        for (int b = 0; b < 4; b++)
#pragma unroll
            for (int c = 0; c < 4; c++) acc[a][b][c] = 0.0f;

#define G_ISSUE(s, buf) do {                                                  \
        const uint32_t d = sb + (uint32_t)((buf) * STG_B) + sdst;             \
        const int go = (s) * GBK;                                             \
        CPA16(d + 0 * ARR_B,      pA + go);                                   \
        CPA16(d + 0 * ARR_B + 16, pA + go + 8);                               \
        CPA16(d + 1 * ARR_B,      pB + go);                                   \
        CPA16(d + 1 * ARR_B + 16, pB + go + 8);                               \
    } while (0)

    G_ISSUE(0, 0); CPCOMMIT();
    G_ISSUE(1, 1); CPCOMMIT();
    G_ISSUE(2, 2); CPCOMMIT();

    int buf = 0;
    for (int t = 0; t < GKT; t++) {
        CPWAIT2();
        __syncthreads();

        const uint32_t stg = sb + (uint32_t)(buf * STG_B);
#pragma unroll
        for (int ks = 0; ks < 2; ks++) {
            uint32_t ah[4][4];
#pragma unroll
            for (int mt = 0; mt < 4; mt++)
                ldsm4(ah[mt], stg + 0 * ARR_B + aoff + mt * 1280 + ks * 32);
            uint32_t bh[4][2];
#pragma unroll
            for (int bt = 0; bt < 2; bt++) {
                uint32_t tmp[4];
                ldsm4(tmp, stg + 1 * ARR_B + boff + bt * 1280 + ks * 32);
                bh[2 * bt][0] = tmp[0]; bh[2 * bt][1] = tmp[1];
                bh[2 * bt + 1][0] = tmp[2]; bh[2 * bt + 1][1] = tmp[3];
            }
#pragma unroll
            for (int mt = 0; mt < 4; mt++)
#pragma unroll
                for (int nt = 0; nt < 4; nt++)
                    mma16816(acc[mt][nt], ah[mt], bh[nt]);
        }
        __syncthreads();
        if (t + 3 < GKT) G_ISSUE(t + 3, buf);
        CPCOMMIT();
        buf = (buf == 2) ? 0 : buf + 1;
    }
#undef G_ISSUE

    const int gr = lane >> 2;
    const int gc = (lane & 3) * 2;
#pragma unroll
    for (int mt = 0; mt < 4; mt++) {
        const int row = m0 + wm * 64 + mt * 16 + gr;
#pragma unroll
        for (int nt = 0; nt < 4; nt++) {
            const int col = n0 + wn * 32 + nt * 8 + gc;
            const size_t i0 = (size_t)row * D_MODEL + col;
            const size_t i1 = (size_t)(row + 8) * D_MODEL + col;
            if (OUT == 0) {
                *(float2*)&C[i0] = make_float2(acc[mt][nt][0], acc[mt][nt][1]);
                *(float2*)&C[i1] = make_float2(acc[mt][nt][2], acc[mt][nt][3]);
            } else {
                *(uint32_t*)(Ch + i0) =
                    packh2(acc[mt][nt][0] * cscale, acc[mt][nt][1] * cscale);
                *(uint32_t*)(Ch + i1) =
                    packh2(acc[mt][nt][2] * cscale, acc[mt][nt][3] * cscale);
            }
        }
    }
}

// fused QKV projection: blockIdx.z selects weight/output; Q pre-scaled by 0.125
__global__ __launch_bounds__(256, 2) void gemm_qkv(
    const __half* __restrict__ xh,
    const __half* __restrict__ wqh, const __half* __restrict__ wkh,
    const __half* __restrict__ wvh,
    __half* __restrict__ qh, __half* __restrict__ kh, __half* __restrict__ vh) {
    extern __shared__ char smc[];
    const __half* Bh;
    __half* Ch;
    float cs = 1.0f;
    if (blockIdx.z == 0)      { Bh = wqh; Ch = qh; cs = 0.125f; }
    else if (blockIdx.z == 1) { Bh = wkh; Ch = kh; }
    else                      { Bh = wvh; Ch = vh; }
    gemm_body<1>(smc, xh, Bh, nullptr, Ch, cs, blockIdx.y * 128, blockIdx.x * 128);
}

__global__ __launch_bounds__(256, 2) void gemm_out(
    const __half* __restrict__ ath, const __half* __restrict__ woh,
    float* __restrict__ out) {
    extern __shared__ char smc[];
    gemm_body<0>(smc, ath, woh, out, nullptr, 1.0f, blockIdx.y * 128, blockIdx.x * 128);
}

// ---------------------------------------------------------------------------
// Flash attention on HMMA, fp16 hi-only operands. Causal.
// 256 threads = 8 warps; Q tile 128 rows (16/warp); KV tiles 64 keys.
// 3-stage cp.async KV pipeline. Q arrives pre-scaled by 1/sqrt(d).
// ---------------------------------------------------------------------------
#define FST 144
#define FARR (64 * FST)        // 9216
#define FSTG (2 * FARR)        // Kh | Vh = 18432
#define FLASH_SMEM (3 * FSTG)  // 55296 (3 stages)

__global__ __launch_bounds__(256) void flash_mma(
    const __half* __restrict__ Qh,
    const __half* __restrict__ Kh, const __half* __restrict__ Vh,
    __half* __restrict__ Oh) {
    extern __shared__ char smc[];
    const uint32_t sb = smem_to_u32(smc);
    const int tid = threadIdx.x;
    const int w = tid >> 5;
    const int lane = tid & 31;
    const int qt = gridDim.x - 1 - blockIdx.x;   // long blocks first
    const int h = blockIdx.y;
    const int b = blockIdx.z;
    const int q0 = qt * 128;
    const int ktmax = 2 * qt + 1;

    const size_t gbase = (size_t)b * SEQL * D_MODEL + h * HEAD_DIM;

    const int r = lane >> 2;
    const int c2 = (lane & 3) * 2;

    const int sa = tid >> 7;            // 0 = Kh, 1 = Vh
    const int t2 = tid & 127;
    const int srow = t2 >> 1;
    const int shalf = t2 & 1;
    const __half* kvsrc = (sa == 0 ? Kh : Vh) + gbase + (size_t)srow * D_MODEL + shalf * 32;
    const uint32_t kvdst = (uint32_t)(sa * FARR + srow * FST + shalf * 64);

    const uint32_t qaddr = sb + (uint32_t)((w * 16 + (lane & 15)) * FST + (lane >> 4) * 16);
    const uint32_t koff = (uint32_t)(((((lane >> 4) << 3) + (lane & 7)) * FST) + ((lane >> 3) & 1) * 16);
    const uint32_t voff = (uint32_t)((((((lane >> 3) & 1) * 8) + (lane & 7)) * FST) + (lane >> 4) * 16) + FARR;

    // ---- stage Q (128 rows x 128 B) into buffer 0, grab fragments ----
    {
        const int qrow = tid >> 1;
        const int qhalf = tid & 1;
        const uint32_t d = sb + (uint32_t)(qrow * FST + qhalf * 64);
        const __half* s = Qh + gbase + (size_t)(q0 + qrow) * D_MODEL + qhalf * 32;
#pragma unroll
        for (int j = 0; j < 4; j++) CPA16(d + j * 16, s + j * 8);
    }
    CPCOMMIT(); CPWAIT0();
    __syncthreads();
    uint32_t qhf[4][4];
#pragma unroll
    for (int ks = 0; ks < 4; ks++)
        ldsm4(qhf[ks], qaddr + ks * 32);
    __syncthreads();

#define F_STAGE(kt, buf) do {                                                 \
        const uint32_t d = sb + (uint32_t)((buf) * FSTG) + kvdst;             \
        const __half* s = kvsrc + (size_t)(kt) * 64 * D_MODEL;                \
        CPA16(d + 0,  s);      CPA16(d + 16, s + 8);                          \
        CPA16(d + 32, s + 16); CPA16(d + 48, s + 24);                         \
    } while (0)

    F_STAGE(0, 0); CPCOMMIT();
    if (1 <= ktmax) F_STAGE(1, 1);
    CPCOMMIT();

    float o[8][4];
#pragma unroll
    for (int nt = 0; nt < 8; nt++)
#pragma unroll
        for (int j = 0; j < 4; j++) o[nt][j] = 0.0f;
    float mA = -1e30f, mB = -1e30f, lA = 0.0f, lB = 0.0f;

    int buf = 0;
    int buf2 = 2;   // buffer for kt+2
    for (int kt = 0; kt <= ktmax; kt++) {
        if (kt + 2 <= ktmax) F_STAGE(kt + 2, buf2);
        CPCOMMIT();
        CPWAIT2();
        __syncthreads();

        const uint32_t stg = sb + (uint32_t)(buf * FSTG);
        const int k0 = kt * 64;

        // ---- S = Qs Kh^T (Q pre-scaled) ----
        float s[8][4];
#pragma unroll
        for (int nt = 0; nt < 8; nt++)
#pragma unroll
            for (int j = 0; j < 4; j++) s[nt][j] = 0.0f;

#pragma unroll
        for (int ks = 0; ks < 4; ks++) {
#pragma unroll
            for (int np = 0; np < 4; np++) {
                uint32_t th[4];
                ldsm4(th, stg + koff + np * 16 * FST + ks * 32);
                mma16816(s[2 * np],     qhf[ks], th);
                mma16816(s[2 * np + 1], qhf[ks], th + 2);
            }
        }

        // ---- causal mask (only last two kt tiles can cross diag) ----
        const bool masked = (kt >= 2 * qt);
        if (masked) {
            const int rowA = q0 + w * 16 + r;
            const int rowB = rowA + 8;
#pragma unroll
            for (int nt = 0; nt < 8; nt++)
#pragma unroll
                for (int j = 0; j < 2; j++) {
                    const int colg = k0 + nt * 8 + c2 + j;
                    if (colg > rowA) s[nt][j] = -1e30f;
                    if (colg > rowB) s[nt][j + 2] = -1e30f;
                }
        }

        // ---- online softmax ----
        float mxA = -1e30f, mxB = -1e30f;
#pragma unroll
        for (int nt = 0; nt < 8; nt++) {
            mxA = fmaxf(mxA, fmaxf(s[nt][0], s[nt][1]));
            mxB = fmaxf(mxB, fmaxf(s[nt][2], s[nt][3]));
        }
        mxA = fmaxf(mxA, __shfl_xor_sync(0xffffffffu, mxA, 1));
        mxA = fmaxf(mxA, __shfl_xor_sync(0xffffffffu, mxA, 2));
        mxB = fmaxf(mxB, __shfl_xor_sync(0xffffffffu, mxB, 1));
        mxB = fmaxf(mxB, __shfl_xor_sync(0xffffffffu, mxB, 2));
        const float mnA = fmaxf(mA, mxA);
        const float mnB = fmaxf(mB, mxB);
        float suA = 0.0f, suB = 0.0f;
#pragma unroll
        for (int nt = 0; nt < 8; nt++) {
            float e0 = __expf(s[nt][0] - mnA);
            float e1 = __expf(s[nt][1] - mnA);
            float e2 = __expf(s[nt][2] - mnB);
            float e3 = __expf(s[nt][3] - mnB);
            s[nt][0] = e0; s[nt][1] = e1; s[nt][2] = e2; s[nt][3] = e3;
            suA += e0 + e1;
            suB += e2 + e3;
        }
        suA += __shfl_xor_sync(0xffffffffu, suA, 1);
        suA += __shfl_xor_sync(0xffffffffu, suA, 2);
        suB += __shfl_xor_sync(0xffffffffu, suB, 1);
        suB += __shfl_xor_sync(0xffffffffu, suB, 2);
        const float scA = __expf(mA - mnA);
        const float scB = __expf(mB - mnB);
        mA = mnA; mB = mnB;
        lA = lA * scA + suA;
        lB = lB * scB + suB;
#pragma unroll
        for (int nt = 0; nt < 8; nt++) {
            o[nt][0] *= scA; o[nt][1] *= scA;
            o[nt][2] *= scB; o[nt][3] *= scB;
        }

        // ---- O += Ph Vh ----
#pragma unroll
        for (int ks = 0; ks < 4; ks++) {
            uint32_t pha[4];
            pha[0] = packh2(s[2 * ks][0], s[2 * ks][1]);
            pha[1] = packh2(s[2 * ks][2], s[2 * ks][3]);
            pha[2] = packh2(s[2 * ks + 1][0], s[2 * ks + 1][1]);
            pha[3] = packh2(s[2 * ks + 1][2], s[2 * ks + 1][3]);
#pragma unroll
            for (int np = 0; np < 4; np++) {
                uint32_t th[4];
                ldsm4t(th, stg + voff + ks * 16 * FST + np * 32);
                mma16816(o[2 * np],     pha, th);
                mma16816(o[2 * np + 1], pha, th + 2);
            }
        }
        __syncthreads();
        buf  = (buf  == 2) ? 0 : buf + 1;
        buf2 = (buf2 == 2) ? 0 : buf2 + 1;
    }
#undef F_STAGE

    // ---- epilogue: normalize, store fp16 hi ----
    const float liA = 1.0f / lA;
    const float liB = 1.0f / lB;
    const size_t orA = gbase + (size_t)(q0 + w * 16 + r) * D_MODEL;
    const size_t orB = orA + (size_t)8 * D_MODEL;
#pragma unroll
    for (int nt = 0; nt < 8; nt++) {
        const int col = nt * 8 + c2;
        *(uint32_t*)(Oh + orA + col) = packh2(o[nt][0] * liA, o[nt][1] * liA);
        *(uint32_t*)(Oh + orB + col) = packh2(o[nt][2] * liB, o[nt][3] * liB);
    }
}

// ---------------------------------------------------------------------------
extern "C" void kernel_launch(void* const* d_in, const int* in_sizes, int n_in,
                              void* d_out, int out_size) {
    const float* x  = (const float*)d_in[0];
    const float* wq = (const float*)d_in[1];
    const float* wk = (const float*)d_in[2];
    const float* wv = (const float*)d_in[3];
    const float* wo = (const float*)d_in[4];
    float* out = (float*)d_out;

    __half *xh, *qh, *kh, *vh, *ath, *wqh, *wkh, *wvh, *woh;
    cudaGetSymbolAddress((void**)&xh, g_xh);
    cudaGetSymbolAddress((void**)&qh, g_qh);
    cudaGetSymbolAddress((void**)&kh, g_kh);
    cudaGetSymbolAddress((void**)&vh, g_vh);
    cudaGetSymbolAddress((void**)&ath, g_ath);
    cudaGetSymbolAddress((void**)&wqh, g_wqh);
    cudaGetSymbolAddress((void**)&wkh, g_wkh);
    cudaGetSymbolAddress((void**)&wvh, g_wvh);
    cudaGetSymbolAddress((void**)&woh, g_woh);

    cudaFuncSetAttribute(gemm_qkv, cudaFuncAttributeMaxDynamicSharedMemorySize, GEMM_SMEM);
    cudaFuncSetAttribute(gemm_out, cudaFuncAttributeMaxDynamicSharedMemorySize, GEMM_SMEM);
    cudaFuncSetAttribute(flash_mma, cudaFuncAttributeMaxDynamicSharedMemorySize, FLASH_SMEM);

    const int nx4 = MROWS * D_MODEL / 4;
    const int nw4 = D_MODEL * D_MODEL / 4;

    cvt_h_k<<<(nx4 + 255) / 256, 256>>>((const float4*)x, (uint32_t*)xh, nx4);
    cvt4_h_k<<<dim3((nw4 + 255) / 256, 4), 256>>>(
        (const float4*)wq, (const float4*)wk, (const float4*)wv, (const float4*)wo,
        (uint32_t*)wqh, (uint32_t*)wkh, (uint32_t*)wvh, (uint32_t*)woh, nw4);

    gemm_qkv<<<dim3(D_MODEL / 128, MROWS / 128, 3), 256, GEMM_SMEM>>>(
        xh, wqh, wkh, wvh, qh, kh, vh);

    flash_mma<<<dim3(SEQL / 128, N_HEADS, BATCH), 256, FLASH_SMEM>>>(qh, kh, vh, ath);

    gemm_out<<<dim3(D_MODEL / 128, MROWS / 128), 256, GEMM_SMEM>>>(ath, woh, out);
}

// round 11
// speedup vs baseline: 1.6696x; 1.0765x over previous
#include <cuda_runtime.h>
#include <cuda_fp16.h>
#include <cstdint>
#include <math.h>

#define D_MODEL 1024
#define N_HEADS 16
#define HEAD_DIM 64
#define BATCH 2
#define SEQL 2048
#define MROWS (BATCH * SEQL)   // 4096

// ---------------- scratch (device globals: allocation-free rule) -----------
__device__ __half g_xh[MROWS * D_MODEL];
__device__ __half g_qh[MROWS * D_MODEL];
__device__ __half g_kh[MROWS * D_MODEL];
__device__ __half g_vh[MROWS * D_MODEL];
__device__ __half g_ath[MROWS * D_MODEL];
__device__ __half g_wqh[D_MODEL * D_MODEL];
__device__ __half g_wkh[D_MODEL * D_MODEL];
__device__ __half g_wvh[D_MODEL * D_MODEL];
__device__ __half g_woh[D_MODEL * D_MODEL];

// ---------------- helpers ---------------------------------------------------
__device__ __forceinline__ uint32_t smem_to_u32(const void* p) {
    uint32_t a;
    asm("{ .reg .u64 t; cvta.to.shared.u64 t, %1; cvt.u32.u64 %0, t; }" : "=r"(a) : "l"(p));
    return a;
}

#define CPA16(dst, src) \
    asm volatile("cp.async.cg.shared.global [%0], [%1], 16;" :: "r"(dst), "l"(src) : "memory")
#define CPCOMMIT() asm volatile("cp.async.commit_group;" ::: "memory")
#define CPWAIT0() asm volatile("cp.async.wait_group 0;" ::: "memory")
#define CPWAIT2() asm volatile("cp.async.wait_group 2;" ::: "memory")

__device__ __forceinline__ void ldsm4(uint32_t* r, uint32_t addr) {
    asm volatile("ldmatrix.sync.aligned.m8n8.x4.shared.b16 {%0,%1,%2,%3}, [%4];"
                 : "=r"(r[0]), "=r"(r[1]), "=r"(r[2]), "=r"(r[3]) : "r"(addr));
}

__device__ __forceinline__ void ldsm4t(uint32_t* r, uint32_t addr) {
    asm volatile("ldmatrix.sync.aligned.m8n8.x4.trans.shared.b16 {%0,%1,%2,%3}, [%4];"
                 : "=r"(r[0]), "=r"(r[1]), "=r"(r[2]), "=r"(r[3]) : "r"(addr));
}

__device__ __forceinline__ void mma16816(float* d, const uint32_t* a, const uint32_t* b) {
    asm volatile(
        "mma.sync.aligned.m16n8k16.row.col.f32.f16.f16.f32 "
        "{%0,%1,%2,%3}, {%4,%5,%6,%7}, {%8,%9}, {%0,%1,%2,%3};"
        : "+f"(d[0]), "+f"(d[1]), "+f"(d[2]), "+f"(d[3])
        : "r"(a[0]), "r"(a[1]), "r"(a[2]), "r"(a[3]), "r"(b[0]), "r"(b[1]));
}

__device__ __forceinline__ uint32_t packh2(float x, float y) {
    __half2 h = __floats2half2_rn(x, y);
    return *(uint32_t*)&h;
}

__device__ __forceinline__ float ex2f(float x) {
    float y;
    asm("ex2.approx.f32 %0, %1;" : "=f"(y) : "f"(x));
    return y;
}

// ---------------------------------------------------------------------------
// converts
// ---------------------------------------------------------------------------
__global__ __launch_bounds__(256) void cvt_h_k(const float4* __restrict__ in,
                                               uint32_t* __restrict__ hi, int n4) {
    int i = blockIdx.x * blockDim.x + threadIdx.x;
    if (i >= n4) return;
    float4 v = in[i];
    hi[2 * i]     = packh2(v.x, v.y);
    hi[2 * i + 1] = packh2(v.z, v.w);
}

__global__ __launch_bounds__(256) void cvt4_h_k(
    const float4* __restrict__ w0, const float4* __restrict__ w1,
    const float4* __restrict__ w2, const float4* __restrict__ w3,
    uint32_t* __restrict__ h0, uint32_t* __restrict__ h1,
    uint32_t* __restrict__ h2, uint32_t* __restrict__ h3, int n4) {
    int i = blockIdx.x * blockDim.x + threadIdx.x;
    if (i >= n4) return;
    const float4* in; uint32_t* hi;
    switch (blockIdx.y) {
        case 0:  in = w0; hi = h0; break;
        case 1:  in = w1; hi = h1; break;
        case 2:  in = w2; hi = h2; break;
        default: in = w3; hi = h3; break;
    }
    float4 v = in[i];
    hi[2 * i]     = packh2(v.x, v.y);
    hi[2 * i + 1] = packh2(v.z, v.w);
}

// ---------------------------------------------------------------------------
// HMMA fp16 1-pass GEMM-NT: C[m,n] = sum_k A[m,k]*B[n,k]
// CTA 128x128, BK=32, 4-stage cp.async pipeline, ONE sync per k-tile.
// OUT: 0 = fp32 C, 1 = fp16 hi (Ch, scaled by cscale)
// ---------------------------------------------------------------------------
#define GBK 32
#define GKT (D_MODEL / GBK)          // 32
#define ARR_B 10240                  // 128 rows * 80 B
#define STG_B (2 * ARR_B)            // A | B = 20480
#define GEMM_SMEM (4 * STG_B)        // 81920 (4 stages)

template <int OUT>
__device__ __forceinline__ void gemm_body(
    char* smc, const __half* __restrict__ Ah, const __half* __restrict__ Bh,
    float* __restrict__ C, __half* __restrict__ Ch, float cscale,
    int m0, int n0) {
    const uint32_t sb = smem_to_u32(smc);
    const int tid = threadIdx.x;
    const int wid = tid >> 5;
    const int lane = tid & 31;
    const int wm = wid >> 2;
    const int wn = wid & 3;

    const int lrow = tid >> 1;
    const int lhof = (tid & 1) * 16;
    const __half* pA = Ah + (size_t)(m0 + lrow) * D_MODEL + lhof;
    const __half* pB = Bh + (size_t)(n0 + lrow) * D_MODEL + lhof;
    const uint32_t sdst = (uint32_t)(lrow * 80 + (tid & 1) * 32);

    const uint32_t aoff = (uint32_t)((wm * 64 + (lane & 15)) * 80 + (lane >> 4) * 16);
    const int j8 = lane >> 3;
    const uint32_t boff = (uint32_t)((wn * 32 + ((j8 >> 1) << 3) + (lane & 7)) * 80 + (j8 & 1) * 16);

    float acc[4][4][4];
#pragma unroll
    for (int a = 0; a < 4; a++)
#pragma unroll
        for (int b = 0; b < 4; b++)
#pragma unroll
            for (int c = 0; c < 4; c++) acc[a][b][c] = 0.0f;

#define G_ISSUE(s) do {                                                       \
        const uint32_t d = sb + (uint32_t)((((s) & 3)) * STG_B) + sdst;       \
        const int go = (s) * GBK;                                             \
        CPA16(d + 0 * ARR_B,      pA + go);                                   \
        CPA16(d + 0 * ARR_B + 16, pA + go + 8);                               \
        CPA16(d + 1 * ARR_B,      pB + go);                                   \
        CPA16(d + 1 * ARR_B + 16, pB + go + 8);                               \
    } while (0)

    G_ISSUE(0); CPCOMMIT();
    G_ISSUE(1); CPCOMMIT();
    G_ISSUE(2); CPCOMMIT();

    for (int t = 0; t < GKT; t++) {
        CPWAIT2();
        __syncthreads();
        // issue t+3 into buffer (t+3)&3 == (t-1)&3: drained by the sync above
        if (t + 3 < GKT) G_ISSUE(t + 3);
        CPCOMMIT();

        const uint32_t stg = sb + (uint32_t)((t & 3) * STG_B);
#pragma unroll
        for (int ks = 0; ks < 2; ks++) {
            uint32_t ah[4][4];
#pragma unroll
            for (int mt = 0; mt < 4; mt++)
                ldsm4(ah[mt], stg + 0 * ARR_B + aoff + mt * 1280 + ks * 32);
            uint32_t bh[4][2];
#pragma unroll
            for (int bt = 0; bt < 2; bt++) {
                uint32_t tmp[4];
                ldsm4(tmp, stg + 1 * ARR_B + boff + bt * 1280 + ks * 32);
                bh[2 * bt][0] = tmp[0]; bh[2 * bt][1] = tmp[1];
                bh[2 * bt + 1][0] = tmp[2]; bh[2 * bt + 1][1] = tmp[3];
            }
#pragma unroll
            for (int mt = 0; mt < 4; mt++)
#pragma unroll
                for (int nt = 0; nt < 4; nt++)
                    mma16816(acc[mt][nt], ah[mt], bh[nt]);
        }
    }
#undef G_ISSUE

    const int gr = lane >> 2;
    const int gc = (lane & 3) * 2;
#pragma unroll
    for (int mt = 0; mt < 4; mt++) {
        const int row = m0 + wm * 64 + mt * 16 + gr;
#pragma unroll
        for (int nt = 0; nt < 4; nt++) {
            const int col = n0 + wn * 32 + nt * 8 + gc;
            const size_t i0 = (size_t)row * D_MODEL + col;
            const size_t i1 = (size_t)(row + 8) * D_MODEL + col;
            if (OUT == 0) {
                *(float2*)&C[i0] = make_float2(acc[mt][nt][0], acc[mt][nt][1]);
                *(float2*)&C[i1] = make_float2(acc[mt][nt][2], acc[mt][nt][3]);
            } else {
                *(uint32_t*)(Ch + i0) =
                    packh2(acc[mt][nt][0] * cscale, acc[mt][nt][1] * cscale);
                *(uint32_t*)(Ch + i1) =
                    packh2(acc[mt][nt][2] * cscale, acc[mt][nt][3] * cscale);
            }
        }
    }
}

// fused QKV projection. Q pre-scaled by log2(e)/sqrt(d) for base-2 softmax.
#define QSCALE 0.180336880f   // 0.125 * 1.44269504

__global__ __launch_bounds__(256, 2) void gemm_qkv(
    const __half* __restrict__ xh,
    const __half* __restrict__ wqh, const __half* __restrict__ wkh,
    const __half* __restrict__ wvh,
    __half* __restrict__ qh, __half* __restrict__ kh, __half* __restrict__ vh) {
    extern __shared__ char smc[];
    const __half* Bh;
    __half* Ch;
    float cs = 1.0f;
    if (blockIdx.z == 0)      { Bh = wqh; Ch = qh; cs = QSCALE; }
    else if (blockIdx.z == 1) { Bh = wkh; Ch = kh; }
    else                      { Bh = wvh; Ch = vh; }
    gemm_body<1>(smc, xh, Bh, nullptr, Ch, cs, blockIdx.y * 128, blockIdx.x * 128);
}

__global__ __launch_bounds__(256, 2) void gemm_out(
    const __half* __restrict__ ath, const __half* __restrict__ woh,
    float* __restrict__ out) {
    extern __shared__ char smc[];
    gemm_body<0>(smc, ath, woh, out, nullptr, 1.0f, blockIdx.y * 128, blockIdx.x * 128);
}

// ---------------------------------------------------------------------------
// Flash attention on HMMA, fp16 hi-only, base-2 softmax. Causal.
// 256 threads = 8 warps; Q tile 128 rows; KV tiles 64 keys.
// 4-stage cp.async KV pipeline, ONE sync per tile.
// ---------------------------------------------------------------------------
#define FST 144
#define FARR (64 * FST)        // 9216
#define FSTG (2 * FARR)        // Kh | Vh = 18432
#define FLASH_SMEM (4 * FSTG)  // 73728 (4 stages)

__global__ __launch_bounds__(256) void flash_mma(
    const __half* __restrict__ Qh,
    const __half* __restrict__ Kh, const __half* __restrict__ Vh,
    __half* __restrict__ Oh) {
    extern __shared__ char smc[];
    const uint32_t sb = smem_to_u32(smc);
    const int tid = threadIdx.x;
    const int w = tid >> 5;
    const int lane = tid & 31;
    const int qt = gridDim.x - 1 - blockIdx.x;   // long blocks first
    const int h = blockIdx.y;
    const int b = blockIdx.z;
    const int q0 = qt * 128;
    const int ktmax = 2 * qt + 1;

    const size_t gbase = (size_t)b * SEQL * D_MODEL + h * HEAD_DIM;

    const int r = lane >> 2;
    const int c2 = (lane & 3) * 2;

    const int sa = tid >> 7;            // 0 = Kh, 1 = Vh
    const int t2 = tid & 127;
    const int srow = t2 >> 1;
    const int shalf = t2 & 1;
    const __half* kvsrc = (sa == 0 ? Kh : Vh) + gbase + (size_t)srow * D_MODEL + shalf * 32;
    const uint32_t kvdst = (uint32_t)(sa * FARR + srow * FST + shalf * 64);

    const uint32_t qaddr = sb + (uint32_t)((w * 16 + (lane & 15)) * FST + (lane >> 4) * 16);
    const uint32_t koff = (uint32_t)(((((lane >> 4) << 3) + (lane & 7)) * FST) + ((lane >> 3) & 1) * 16);
    const uint32_t voff = (uint32_t)((((((lane >> 3) & 1) * 8) + (lane & 7)) * FST) + (lane >> 4) * 16) + FARR;

    // ---- stage Q (128 rows x 128 B) through stage-0 region, grab fragments ----
    {
        const int qrow = tid >> 1;
        const int qhalf = tid & 1;
        const uint32_t d = sb + (uint32_t)(qrow * FST + qhalf * 64);
        const __half* s = Qh + gbase + (size_t)(q0 + qrow) * D_MODEL + qhalf * 32;
#pragma unroll
        for (int j = 0; j < 4; j++) CPA16(d + j * 16, s + j * 8);
    }
    CPCOMMIT(); CPWAIT0();
    __syncthreads();
    uint32_t qhf[4][4];
#pragma unroll
    for (int ks = 0; ks < 4; ks++)
        ldsm4(qhf[ks], qaddr + ks * 32);
    __syncthreads();

#define F_STAGE(kt) do {                                                      \
        const uint32_t d = sb + (uint32_t)(((kt) & 3) * FSTG) + kvdst;        \
        const __half* s = kvsrc + (size_t)(kt) * 64 * D_MODEL;                \
        CPA16(d + 0,  s);      CPA16(d + 16, s + 8);                          \
        CPA16(d + 32, s + 16); CPA16(d + 48, s + 24);                         \
    } while (0)

    F_STAGE(0); CPCOMMIT();
    if (1 <= ktmax) F_STAGE(1);
    CPCOMMIT();
    if (2 <= ktmax) F_STAGE(2);
    CPCOMMIT();

    float o[8][4];
#pragma unroll
    for (int nt = 0; nt < 8; nt++)
#pragma unroll
        for (int j = 0; j < 4; j++) o[nt][j] = 0.0f;
    float mA = -1e30f, mB = -1e30f, lA = 0.0f, lB = 0.0f;

    for (int kt = 0; kt <= ktmax; kt++) {
        CPWAIT2();
        __syncthreads();
        // issue kt+3 into buffer (kt+3)&3 == (kt-1)&3: drained by the sync above
        if (kt + 3 <= ktmax) F_STAGE(kt + 3);
        CPCOMMIT();

        const uint32_t stg = sb + (uint32_t)((kt & 3) * FSTG);
        const int k0 = kt * 64;

        // ---- S = Qs Kh^T (Q pre-scaled by log2e/sqrt(d); S in log2 units) ----
        float s[8][4];
#pragma unroll
        for (int nt = 0; nt < 8; nt++)
#pragma unroll
            for (int j = 0; j < 4; j++) s[nt][j] = 0.0f;

#pragma unroll
        for (int ks = 0; ks < 4; ks++) {
#pragma unroll
            for (int np = 0; np < 4; np++) {
                uint32_t th[4];
                ldsm4(th, stg + koff + np * 16 * FST + ks * 32);
                mma16816(s[2 * np],     qhf[ks], th);
                mma16816(s[2 * np + 1], qhf[ks], th + 2);
            }
        }

        // ---- causal mask ----
        const bool masked = (kt >= 2 * qt);
        if (masked) {
            const int rowA = q0 + w * 16 + r;
            const int rowB = rowA + 8;
#pragma unroll
            for (int nt = 0; nt < 8; nt++)
#pragma unroll
                for (int j = 0; j < 2; j++) {
                    const int colg = k0 + nt * 8 + c2 + j;
                    if (colg > rowA) s[nt][j] = -1e30f;
                    if (colg > rowB) s[nt][j + 2] = -1e30f;
                }
        }

        // ---- online softmax (base-2) ----
        float mxA = -1e30f, mxB = -1e30f;
#pragma unroll
        for (int nt = 0; nt < 8; nt++) {
            mxA = fmaxf(mxA, fmaxf(s[nt][0], s[nt][1]));
            mxB = fmaxf(mxB, fmaxf(s[nt][2], s[nt][3]));
        }
        mxA = fmaxf(mxA, __shfl_xor_sync(0xffffffffu, mxA, 1));
        mxA = fmaxf(mxA, __shfl_xor_sync(0xffffffffu, mxA, 2));
        mxB = fmaxf(mxB, __shfl_xor_sync(0xffffffffu, mxB, 1));
        mxB = fmaxf(mxB, __shfl_xor_sync(0xffffffffu, mxB, 2));
        const float mnA = fmaxf(mA, mxA);
        const float mnB = fmaxf(mB, mxB);
        float suA = 0.0f, suB = 0.0f;
#pragma unroll
        for (int nt = 0; nt < 8; nt++) {
            float e0 = ex2f(s[nt][0] - mnA);
            float e1 = ex2f(s[nt][1] - mnA);
            float e2 = ex2f(s[nt][2] - mnB);
            float e3 = ex2f(s[nt][3] - mnB);
            s[nt][0] = e0; s[nt][1] = e1; s[nt][2] = e2; s[nt][3] = e3;
            suA += e0 + e1;
            suB += e2 + e3;
        }
        suA += __shfl_xor_sync(0xffffffffu, suA, 1);
        suA += __shfl_xor_sync(0xffffffffu, suA, 2);
        suB += __shfl_xor_sync(0xffffffffu, suB, 1);
        suB += __shfl_xor_sync(0xffffffffu, suB, 2);
        const float scA = ex2f(mA - mnA);
        const float scB = ex2f(mB - mnB);
        mA = mnA; mB = mnB;
        lA = lA * scA + suA;
        lB = lB * scB + suB;
#pragma unroll
        for (int nt = 0; nt < 8; nt++) {
            o[nt][0] *= scA; o[nt][1] *= scA;
            o[nt][2] *= scB; o[nt][3] *= scB;
        }

        // ---- O += Ph Vh ----
#pragma unroll
        for (int ks = 0; ks < 4; ks++) {
            uint32_t pha[4];
            pha[0] = packh2(s[2 * ks][0], s[2 * ks][1]);
            pha[1] = packh2(s[2 * ks][2], s[2 * ks][3]);
            pha[2] = packh2(s[2 * ks + 1][0], s[2 * ks + 1][1]);
            pha[3] = packh2(s[2 * ks + 1][2], s[2 * ks + 1][3]);
#pragma unroll
            for (int np = 0; np < 4; np++) {
                uint32_t th[4];
                ldsm4t(th, stg + voff + ks * 16 * FST + np * 32);
                mma16816(o[2 * np],     pha, th);
                mma16816(o[2 * np + 1], pha, th + 2);
            }
        }
    }
#undef F_STAGE

    // ---- epilogue: normalize, store fp16 hi ----
    const float liA = 1.0f / lA;
    const float liB = 1.0f / lB;
    const size_t orA = gbase + (size_t)(q0 + w * 16 + r) * D_MODEL;
    const size_t orB = orA + (size_t)8 * D_MODEL;
#pragma unroll
    for (int nt = 0; nt < 8; nt++) {
        const int col = nt * 8 + c2;
        *(uint32_t*)(Oh + orA + col) = packh2(o[nt][0] * liA, o[nt][1] * liA);
        *(uint32_t*)(Oh + orB + col) = packh2(o[nt][2] * liB, o[nt][3] * liB);
    }
}

// ---------------------------------------------------------------------------
extern "C" void kernel_launch(void* const* d_in, const int* in_sizes, int n_in,
                              void* d_out, int out_size) {
    const float* x  = (const float*)d_in[0];
    const float* wq = (const float*)d_in[1];
    const float* wk = (const float*)d_in[2];
    const float* wv = (const float*)d_in[3];
    const float* wo = (const float*)d_in[4];
    float* out = (float*)d_out;

    __half *xh, *qh, *kh, *vh, *ath, *wqh, *wkh, *wvh, *woh;
    cudaGetSymbolAddress((void**)&xh, g_xh);
    cudaGetSymbolAddress((void**)&qh, g_qh);
    cudaGetSymbolAddress((void**)&kh, g_kh);
    cudaGetSymbolAddress((void**)&vh, g_vh);
    cudaGetSymbolAddress((void**)&ath, g_ath);
    cudaGetSymbolAddress((void**)&wqh, g_wqh);
    cudaGetSymbolAddress((void**)&wkh, g_wkh);
    cudaGetSymbolAddress((void**)&wvh, g_wvh);
    cudaGetSymbolAddress((void**)&woh, g_woh);

    cudaFuncSetAttribute(gemm_qkv, cudaFuncAttributeMaxDynamicSharedMemorySize, GEMM_SMEM);
    cudaFuncSetAttribute(gemm_out, cudaFuncAttributeMaxDynamicSharedMemorySize, GEMM_SMEM);
    cudaFuncSetAttribute(flash_mma, cudaFuncAttributeMaxDynamicSharedMemorySize, FLASH_SMEM);

    const int nx4 = MROWS * D_MODEL / 4;
    const int nw4 = D_MODEL * D_MODEL / 4;

    cvt_h_k<<<(nx4 + 255) / 256, 256>>>((const float4*)x, (uint32_t*)xh, nx4);
    cvt4_h_k<<<dim3((nw4 + 255) / 256, 4), 256>>>(
        (const float4*)wq, (const float4*)wk, (const float4*)wv, (const float4*)wo,
        (uint32_t*)wqh, (uint32_t*)wkh, (uint32_t*)wvh, (uint32_t*)woh, nw4);

    gemm_qkv<<<dim3(D_MODEL / 128, MROWS / 128, 3), 256, GEMM_SMEM>>>(
        xh, wqh, wkh, wvh, qh, kh, vh);

    flash_mma<<<dim3(SEQL / 128, N_HEADS, BATCH), 256, FLASH_SMEM>>>(qh, kh, vh, ath);

    gemm_out<<<dim3(D_MODEL / 128, MROWS / 128), 256, GEMM_SMEM>>>(ath, woh, out);
}